// round 11
// baseline (speedup 1.0000x reference)
#include <cuda_runtime.h>
#include <cuda_fp16.h>
#include <math.h>

#define N_NODES 50000
#define N_EDGES 800000
#define DIN 128
#define NH 4
#define WT_TILE (128 * 136)   // one prepped W column-tile (halfs)

// ---------------- scratch buffers -------------------------------------------
__device__ __half g_feath[(size_t)N_NODES * 256];  // GEMM output fp16 (max HF=256)
__device__ __half g_x16[(size_t)N_NODES * 128];    // x converted to fp16
__device__ __half g_bufA[(size_t)N_NODES * 128];   // activations fp16
__device__ __half g_bufB[(size_t)N_NODES * 128];
__device__ __half g_wt[5 * WT_TILE];               // prepped W tiles
__device__ float  g_el[(size_t)N_NODES * NH];
__device__ float  g_er[(size_t)N_NODES * NH];
__device__ int    g_cnt[N_NODES];                  // zero-init; re-zeroed by scan1
__device__ int    g_rptr[N_NODES + 1];
__device__ int    g_cursor[N_NODES];
__device__ int    g_bsum[128];
__device__ int    g_srcs[N_EDGES];

__device__ __forceinline__ unsigned s2u(const void* p) {
    unsigned a;
    asm("{ .reg .u64 t; cvta.to.shared.u64 t, %1; cvt.u32.u64 %0, t; }"
        : "=r"(a) : "l"(p));
    return a;
}

// ---------------- x -> fp16 --------------------------------------------------
__global__ void convert_x(const float* __restrict__ x, __half* __restrict__ y) {
    int i = blockIdx.x * blockDim.x + threadIdx.x;   // 8 elems per thread
    const float4* src = (const float4*)x + i * 2;
    float4 a = src[0], b = src[1];
    __half2 h[4];
    h[0] = __floats2half2_rn(a.x, a.y);
    h[1] = __floats2half2_rn(a.z, a.w);
    h[2] = __floats2half2_rn(b.x, b.y);
    h[3] = __floats2half2_rn(b.z, b.w);
    *(uint4*)(y + i * 8) = *(uint4*)h;
}

// ---------------- W prep: fp32 [K][HF] -> fp16 n-major tiles (no swizzle) ----
__global__ void wprep(const float* __restrict__ w0, const float* __restrict__ w1,
                      const float* __restrict__ w2, const float* __restrict__ w3) {
    int t = blockIdx.x * 256 + threadIdx.x;
    int y = blockIdx.y;
    const float* W; int HF, ct;
    if (y == 0)      { W = w0; HF = 128; ct = 0; }
    else if (y == 1) { W = w1; HF = 128; ct = 0; }
    else if (y == 2) { W = w2; HF = 128; ct = 0; }
    else if (y == 3) { W = w3; HF = 256; ct = 0; }
    else             { W = w3; HF = 256; ct = 1; }
    int n = t & 127, kp = t >> 7;
    int k = 2 * kp;
    float f0 = W[(size_t)k * HF + ct * 128 + n];
    float f1 = W[(size_t)(k + 1) * HF + ct * 128 + n];
    *(__half2*)&g_wt[(size_t)y * WT_TILE + n * 136 + kp * 2] = __floats2half2_rn(f0, f1);
}

// ---------------- tensor-core GEMM + fused el/er (ldmatrix mainloop) ---------
template<int F>
__global__ void __launch_bounds__(256, 2)
tc_gemm(const __half* __restrict__ h16, const __half* __restrict__ wt,
        const float* __restrict__ al, const float* __restrict__ ar,
        __half* __restrict__ feat, float* __restrict__ el,
        float* __restrict__ er) {
    constexpr int HF = 4 * F;
    constexpr int HT = 128 / F;
    extern __shared__ __half smx[];
    __half* As = smx;                      // [128][136]; reused as feat staging
    __half* Bs = smx + 128 * 136;          // prepped tile [128 n][136], linear copy
    float* sAL = (float*)(smx + 2 * 128 * 136);
    float* sAR = sAL + 128;

    const int ct  = blockIdx.y;
    const int n0  = blockIdx.x * 128;
    const int tid = threadIdx.x;
    const int lane = tid & 31;
    const int wid  = tid >> 5;

    if (tid < 128) { sAL[tid] = al[ct * 128 + tid]; sAR[tid] = ar[ct * 128 + tid]; }

#pragma unroll
    for (int i = 0; i < 8; i++) {
        int id = tid + i * 256;
        int r = id >> 4, c = id & 15;
        int n = n0 + r;
        if (n >= N_NODES) n = 0;
        *(uint4*)&As[r * 136 + c * 8] = *(const uint4*)&h16[(size_t)n * DIN + c * 8];
    }
    const uint4* wsrc = (const uint4*)(wt + (size_t)ct * WT_TILE);
#pragma unroll
    for (int i = 0; i < 9; i++) {
        int id = tid + i * 256;
        if (id < 2176) ((uint4*)Bs)[id] = wsrc[id];
    }
    __syncthreads();

    const int g = lane >> 2, q = lane & 3;
    const int m0 = wid * 16;
    float acc[16][4];
#pragma unroll
    for (int nt = 0; nt < 16; nt++)
        acc[nt][0] = acc[nt][1] = acc[nt][2] = acc[nt][3] = 0.f;

    // ldmatrix lane-address bases (bytes)
    // A x4: matrices: rows m0+(lane&15), col halves (lane>>4)*8
    unsigned aBase = s2u(&As[(m0 + (lane & 15)) * 136 + (lane >> 4) * 8]);
    // B x4 for nt-pair: rows (lane&7) + (lane>>4)*8 (then + ntp*16), col halves ((lane>>3)&1)*8
    unsigned bBase = s2u(&Bs[((lane & 7) + ((lane >> 4) << 3)) * 136 + ((lane >> 3) & 1) * 8]);

#pragma unroll
    for (int ks = 0; ks < 8; ks++) {
        unsigned a0, a1, a2, a3;
        asm volatile("ldmatrix.sync.aligned.m8n8.x4.shared.b16 {%0,%1,%2,%3}, [%4];"
                     : "=r"(a0), "=r"(a1), "=r"(a2), "=r"(a3)
                     : "r"(aBase + ks * 32));
#pragma unroll
        for (int ntp = 0; ntp < 8; ntp++) {
            unsigned b00, b01, b10, b11;
            asm volatile("ldmatrix.sync.aligned.m8n8.x4.shared.b16 {%0,%1,%2,%3}, [%4];"
                         : "=r"(b00), "=r"(b01), "=r"(b10), "=r"(b11)
                         : "r"(bBase + ntp * 4352 + ks * 32));
            int nt = 2 * ntp;
            asm volatile(
                "mma.sync.aligned.m16n8k16.row.col.f32.f16.f16.f32 "
                "{%0,%1,%2,%3}, {%4,%5,%6,%7}, {%8,%9}, {%0,%1,%2,%3};"
                : "+f"(acc[nt][0]), "+f"(acc[nt][1]), "+f"(acc[nt][2]), "+f"(acc[nt][3])
                : "r"(a0), "r"(a1), "r"(a2), "r"(a3), "r"(b00), "r"(b01));
            asm volatile(
                "mma.sync.aligned.m16n8k16.row.col.f32.f16.f16.f32 "
                "{%0,%1,%2,%3}, {%4,%5,%6,%7}, {%8,%9}, {%0,%1,%2,%3};"
                : "+f"(acc[nt + 1][0]), "+f"(acc[nt + 1][1]), "+f"(acc[nt + 1][2]), "+f"(acc[nt + 1][3])
                : "r"(a0), "r"(a1), "r"(a2), "r"(a3), "r"(b10), "r"(b11));
        }
    }

    const int rA = n0 + m0 + g, rB = rA + 8;

    // ---- el/er from fp32 accumulators ----
#pragma unroll
    for (int hh = 0; hh < HT; hh++) {
        float plA = 0.f, prA = 0.f, plB = 0.f, prB = 0.f;
#pragma unroll
        for (int j = 0; j < F / 8; j++) {
            int nt = hh * (F / 8) + j;
            int c = nt * 8 + q * 2;
            float al0 = sAL[c], al1 = sAL[c + 1];
            float ar0 = sAR[c], ar1 = sAR[c + 1];
            plA += acc[nt][0] * al0 + acc[nt][1] * al1;
            prA += acc[nt][0] * ar0 + acc[nt][1] * ar1;
            plB += acc[nt][2] * al0 + acc[nt][3] * al1;
            prB += acc[nt][2] * ar0 + acc[nt][3] * ar1;
        }
        plA += __shfl_xor_sync(~0u, plA, 1); plA += __shfl_xor_sync(~0u, plA, 2);
        prA += __shfl_xor_sync(~0u, prA, 1); prA += __shfl_xor_sync(~0u, prA, 2);
        plB += __shfl_xor_sync(~0u, plB, 1); plB += __shfl_xor_sync(~0u, plB, 2);
        prB += __shfl_xor_sync(~0u, prB, 1); prB += __shfl_xor_sync(~0u, prB, 2);
        if (q == 0) {
            int head = ct * HT + hh;
            if (rA < N_NODES) { el[rA * 4 + head] = plA; er[rA * 4 + head] = prA; }
            if (rB < N_NODES) { el[rB * 4 + head] = plB; er[rB * 4 + head] = prB; }
        }
    }

    // ---- feat: stage in smem (As), then coalesced uint4 stores ----
    __syncthreads();
#pragma unroll
    for (int nt = 0; nt < 16; nt++) {
        int c = nt * 8 + q * 2;
        *(__half2*)&As[(m0 + g) * 136 + c]     = __floats2half2_rn(acc[nt][0], acc[nt][1]);
        *(__half2*)&As[(m0 + 8 + g) * 136 + c] = __floats2half2_rn(acc[nt][2], acc[nt][3]);
    }
    __syncthreads();
#pragma unroll
    for (int i = 0; i < 8; i++) {
        int id = tid + i * 256;
        int r = id >> 4, c = id & 15;
        int n = n0 + r;
        if (n < N_NODES)
            *(uint4*)&feat[(size_t)n * HF + ct * 128 + c * 8] = *(uint4*)&As[r * 136 + c * 8];
    }
}

// ---------------- CSR build (parallel 3-kernel scan) --------------------------
__global__ void hist_kernel(const int* __restrict__ dst) {
    int e = blockIdx.x * blockDim.x + threadIdx.x;
    if (e < N_EDGES) atomicAdd(&g_cnt[dst[e]], 1);
}
__global__ void scan1_kernel() {
    __shared__ int ws[16];
    int t = threadIdx.x;
    int lane = t & 31, w = t >> 5;
    int i = blockIdx.x * 512 + t;
    int v = (i < N_NODES) ? g_cnt[i] : 0;
    if (i < N_NODES) g_cnt[i] = 0;                  // reset for next call
    int x = v;
#pragma unroll
    for (int o = 1; o < 32; o <<= 1) {
        int y = __shfl_up_sync(~0u, x, o);
        if (lane >= o) x += y;
    }
    if (lane == 31) ws[w] = x;
    __syncthreads();
    if (t < 16) {
        int s = ws[t];
#pragma unroll
        for (int o = 1; o < 16; o <<= 1) {
            int y = __shfl_up_sync(0xffffu, s, o, 16);
            if (t >= o) s += y;
        }
        ws[t] = s;
    }
    __syncthreads();
    int off = (w > 0) ? ws[w - 1] : 0;
    int incl = x + off;
    if (i < N_NODES) g_rptr[i] = incl - v;
    if (t == 511) g_bsum[blockIdx.x] = incl;
}
__global__ void scan2_kernel(int nb) {
    int t = threadIdx.x;
    int v = (t < nb) ? g_bsum[t] : 0;
    int lane = t & 31, w = t >> 5;
    __shared__ int ws[4];
    int x = v;
#pragma unroll
    for (int o = 1; o < 32; o <<= 1) {
        int y = __shfl_up_sync(~0u, x, o);
        if (lane >= o) x += y;
    }
    if (lane == 31) ws[w] = x;
    __syncthreads();
    if (t < 4) {
        int s = ws[t];
#pragma unroll
        for (int o = 1; o < 4; o <<= 1) {
            int y = __shfl_up_sync(0xfu, s, o, 4);
            if (t >= o) s += y;
        }
        ws[t] = s;
    }
    __syncthreads();
    int off = (w > 0) ? ws[w - 1] : 0;
    if (t < nb) g_bsum[t] = x + off - v;
}
__global__ void scan3_kernel() {
    int i = blockIdx.x * blockDim.x + threadIdx.x;
    if (i < N_NODES) {
        int r = g_rptr[i] + g_bsum[i >> 9];
        g_rptr[i] = r;
        g_cursor[i] = r;
    }
    if (i == 0) g_rptr[N_NODES] = N_EDGES;
}
__global__ void scatter_kernel(const int* __restrict__ src, const int* __restrict__ dst) {
    int e = blockIdx.x * blockDim.x + threadIdx.x;
    if (e >= N_EDGES) return;
    int pos = atomicAdd(&g_cursor[dst[e]], 1);
    g_srcs[pos] = src[e];
}

// ---------------- GAT aggregation: one warp per dst node ---------------------
template<bool LAST>
__global__ void gat_agg(const __half* __restrict__ feat, const float* __restrict__ el,
                        const float* __restrict__ er, const float* __restrict__ bias,
                        void* __restrict__ outv) {
    int warp = (blockIdx.x * blockDim.x + threadIdx.x) >> 5;
    int lane = threadIdx.x & 31;
    if (warp >= N_NODES) return;
    const int nid = warp;
    const int hl = lane & 3;
    const float er_l = __ldg(&er[nid * 4 + hl]);
    int i = __ldg(&g_rptr[nid]);
    const int end = __ldg(&g_rptr[nid + 1]);

    float den_l = 0.f;

    if (!LAST) {
        const uint2* f2 = (const uint2*)feat;
        const int hsel = lane >> 3;
        float4 accA = make_float4(0, 0, 0, 0);
#pragma unroll 4
        for (; i < end; i++) {
            int s = __ldg(&g_srcs[i]);
            float t = __ldg(&el[s * 4 + hl]) + er_l;
            float ex_l = __expf(fmaxf(t, 0.2f * t));
            den_l += ex_l;
            float ex = __shfl_sync(~0u, ex_l, hsel, 4);
            uint2 u = __ldg(&f2[(size_t)s * 32 + lane]);
            float2 fa = __half22float2(*(__half2*)&u.x);
            float2 fb = __half22float2(*(__half2*)&u.y);
            accA.x += ex * fa.x; accA.y += ex * fa.y;
            accA.z += ex * fb.x; accA.w += ex * fb.y;
        }
        float inv_l = 1.f / fmaxf(den_l, 1e-9f);
        float invh = __shfl_sync(~0u, inv_l, hsel, 4);
        int c0 = 4 * lane;
        float4 bv = *(const float4*)&bias[c0];
        float4 v;
        v.x = accA.x * invh + bv.x;
        v.y = accA.y * invh + bv.y;
        v.z = accA.z * invh + bv.z;
        v.w = accA.w * invh + bv.w;
        v.x = v.x > 0.f ? v.x : expm1f(v.x);
        v.y = v.y > 0.f ? v.y : expm1f(v.y);
        v.z = v.z > 0.f ? v.z : expm1f(v.z);
        v.w = v.w > 0.f ? v.w : expm1f(v.w);
        __half2 h01 = __floats2half2_rn(v.x, v.y);
        __half2 h23 = __floats2half2_rn(v.z, v.w);
        uint2 pack = make_uint2(*(unsigned*)&h01, *(unsigned*)&h23);
        ((uint2*)outv)[(size_t)nid * 32 + lane] = pack;
    } else {
        const uint4* f4 = (const uint4*)feat;
        const int exsrc = (lane & ~3) | (lane >> 3);  // lane owning my head's ex
        float acc[8];
#pragma unroll
        for (int k = 0; k < 8; k++) acc[k] = 0.f;
#pragma unroll 4
        for (; i < end; i++) {
            int s = __ldg(&g_srcs[i]);
            float t = __ldg(&el[s * 4 + hl]) + er_l;
            float ex_l = __expf(fmaxf(t, 0.2f * t));
            den_l += ex_l;
            float ex = __shfl_sync(~0u, ex_l, exsrc);
            uint4 u = __ldg(&f4[(size_t)s * 32 + lane]);
            float2 f0 = __half22float2(*(__half2*)&u.x);
            float2 f1 = __half22float2(*(__half2*)&u.y);
            float2 f2v = __half22float2(*(__half2*)&u.z);
            float2 f3 = __half22float2(*(__half2*)&u.w);
            acc[0] += ex * f0.x;  acc[1] += ex * f0.y;
            acc[2] += ex * f1.x;  acc[3] += ex * f1.y;
            acc[4] += ex * f2v.x; acc[5] += ex * f2v.y;
            acc[6] += ex * f3.x;  acc[7] += ex * f3.y;
        }
        float inv_l = 1.f / fmaxf(den_l, 1e-9f);
        float inv = __shfl_sync(~0u, inv_l, exsrc);
        int c0 = 8 * lane;                           // cols 8l..8l+7, head l>>3
        float p[8];
#pragma unroll
        for (int k = 0; k < 8; k++) p[k] = acc[k] * inv + __ldg(&bias[c0 + k]);
#pragma unroll
        for (int k = 0; k < 8; k++) {
            p[k] += __shfl_xor_sync(~0u, p[k], 8);
            p[k] += __shfl_xor_sync(~0u, p[k], 16);
        }
        if (lane < 8) {
            float* out = (float*)outv;
            float4 y0 = make_float4(0.25f * p[0], 0.25f * p[1], 0.25f * p[2], 0.25f * p[3]);
            float4 y1 = make_float4(0.25f * p[4], 0.25f * p[5], 0.25f * p[6], 0.25f * p[7]);
            *(float4*)&out[(size_t)nid * 64 + 8 * lane]     = y0;
            *(float4*)&out[(size_t)nid * 64 + 8 * lane + 4] = y1;
        }
    }
}

// ---------------- host -------------------------------------------------------
extern "C" void kernel_launch(void* const* d_in, const int* in_sizes, int n_in,
                              void* d_out, int out_size) {
    const float* x   = (const float*)d_in[0];
    const int*   src = (const int*)d_in[1];
    const int*   dst = (const int*)d_in[2];
    const float *W[4], *al[4], *ar[4], *bb[4];
    for (int i = 0; i < 4; i++) {
        W[i]  = (const float*)d_in[3 + i * 4];
        al[i] = (const float*)d_in[4 + i * 4];
        ar[i] = (const float*)d_in[5 + i * 4];
        bb[i] = (const float*)d_in[6 + i * 4];
    }

    __half *feat, *x16, *A, *B, *wt;
    float *el, *er;
    cudaGetSymbolAddress((void**)&feat, g_feath);
    cudaGetSymbolAddress((void**)&x16,  g_x16);
    cudaGetSymbolAddress((void**)&A,    g_bufA);
    cudaGetSymbolAddress((void**)&B,    g_bufB);
    cudaGetSymbolAddress((void**)&wt,   g_wt);
    cudaGetSymbolAddress((void**)&el,   g_el);
    cudaGetSymbolAddress((void**)&er,   g_er);

    const int SMEM = 2 * 128 * 136 * 2 + 2 * 128 * 4;   // 70656 B
    cudaFuncSetAttribute(tc_gemm<32>, cudaFuncAttributeMaxDynamicSharedMemorySize, SMEM);
    cudaFuncSetAttribute(tc_gemm<64>, cudaFuncAttributeMaxDynamicSharedMemorySize, SMEM);

    const int nb = (N_NODES + 511) / 512;               // 98
    const int agg_blocks = (N_NODES * 32 + 255) / 256;
    const dim3 g1((N_NODES + 127) / 128, 1), g2((N_NODES + 127) / 128, 2);

    // ---- prep + CSR; tc_gemm L1 placed as 4th launch (ncu captures #4) ----
    convert_x<<<N_NODES * DIN / (256 * 8), 256>>>(x, x16);
    wprep<<<dim3(32, 5), 256>>>(W[0], W[1], W[2], W[3]);
    hist_kernel<<<(N_EDGES + 511) / 512, 512>>>(dst);
    tc_gemm<32><<<g1, 256, SMEM>>>(x16, wt + 0 * WT_TILE, al[0], ar[0], feat, el, er);
    scan1_kernel<<<nb, 512>>>();
    scan2_kernel<<<1, 128>>>(nb);
    scan3_kernel<<<(N_NODES + 511) / 512, 512>>>();
    scatter_kernel<<<(N_EDGES + 511) / 512, 512>>>(src, dst);

    // layer 1 agg
    gat_agg<false><<<agg_blocks, 256>>>(feat, el, er, bb[0], A);
    // layer 2
    tc_gemm<32><<<g1, 256, SMEM>>>(A, wt + 1 * WT_TILE, al[1], ar[1], feat, el, er);
    gat_agg<false><<<agg_blocks, 256>>>(feat, el, er, bb[1], B);
    // layer 3
    tc_gemm<32><<<g1, 256, SMEM>>>(B, wt + 2 * WT_TILE, al[2], ar[2], feat, el, er);
    gat_agg<false><<<agg_blocks, 256>>>(feat, el, er, bb[2], A);
    // layer 4 (fused head-mean)
    tc_gemm<64><<<g2, 256, SMEM>>>(A, wt + 3 * WT_TILE, al[3], ar[3], feat, el, er);
    gat_agg<true><<<agg_blocks, 256>>>(feat, el, er, bb[3], d_out);
}

// round 12
// speedup vs baseline: 1.0230x; 1.0230x over previous
#include <cuda_runtime.h>
#include <cuda_fp16.h>
#include <math.h>

#define N_NODES 50000
#define N_EDGES 800000
#define DIN 128
#define NH 4
#define WT_TILE (128 * 136)   // one prepped W column-tile (halfs)

// ---------------- scratch buffers -------------------------------------------
__device__ __half g_feath[(size_t)N_NODES * 256];  // GEMM output fp16 (max HF=256)
__device__ __half g_x16[(size_t)N_NODES * 128];    // x converted to fp16
__device__ __half g_bufA[(size_t)N_NODES * 128];   // activations fp16
__device__ __half g_bufB[(size_t)N_NODES * 128];
__device__ __half g_wt[5 * WT_TILE];               // prepped W tiles
__device__ float  g_el[(size_t)N_NODES * NH];
__device__ float  g_er[(size_t)N_NODES * NH];
__device__ int    g_cnt[N_NODES];                  // zero-init; re-zeroed by scan1
__device__ int    g_rptr[N_NODES + 1];
__device__ int    g_cursor[N_NODES];
__device__ int    g_bsum[128];
__device__ int    g_srcs[N_EDGES];

__device__ __forceinline__ unsigned s2u(const void* p) {
    unsigned a;
    asm("{ .reg .u64 t; cvta.to.shared.u64 t, %1; cvt.u32.u64 %0, t; }"
        : "=r"(a) : "l"(p));
    return a;
}

// ---------------- x -> fp16 --------------------------------------------------
__global__ void convert_x(const float* __restrict__ x, __half* __restrict__ y) {
    int i = blockIdx.x * blockDim.x + threadIdx.x;   // 8 elems per thread
    const float4* src = (const float4*)x + i * 2;
    float4 a = src[0], b = src[1];
    __half2 h[4];
    h[0] = __floats2half2_rn(a.x, a.y);
    h[1] = __floats2half2_rn(a.z, a.w);
    h[2] = __floats2half2_rn(b.x, b.y);
    h[3] = __floats2half2_rn(b.z, b.w);
    *(uint4*)(y + i * 8) = *(uint4*)h;
}

// ---------------- W prep: fp32 [K][HF] -> fp16 n-major tiles (no swizzle) ----
__global__ void wprep(const float* __restrict__ w0, const float* __restrict__ w1,
                      const float* __restrict__ w2, const float* __restrict__ w3) {
    int t = blockIdx.x * 256 + threadIdx.x;
    int y = blockIdx.y;
    const float* W; int HF, ct;
    if (y == 0)      { W = w0; HF = 128; ct = 0; }
    else if (y == 1) { W = w1; HF = 128; ct = 0; }
    else if (y == 2) { W = w2; HF = 128; ct = 0; }
    else if (y == 3) { W = w3; HF = 256; ct = 0; }
    else             { W = w3; HF = 256; ct = 1; }
    int n = t & 127, kp = t >> 7;
    int k = 2 * kp;
    float f0 = W[(size_t)k * HF + ct * 128 + n];
    float f1 = W[(size_t)(k + 1) * HF + ct * 128 + n];
    *(__half2*)&g_wt[(size_t)y * WT_TILE + n * 136 + kp * 2] = __floats2half2_rn(f0, f1);
}

// ---------------- tensor-core GEMM + fused el/er (ldmatrix mainloop) ---------
template<int F>
__global__ void __launch_bounds__(256, 2)
tc_gemm(const __half* __restrict__ h16, const __half* __restrict__ wt,
        const float* __restrict__ al, const float* __restrict__ ar,
        __half* __restrict__ feat, float* __restrict__ el,
        float* __restrict__ er) {
    constexpr int HF = 4 * F;
    constexpr int HT = 128 / F;
    extern __shared__ __half smx[];
    __half* As = smx;                      // [128][136]; reused as feat staging
    __half* Bs = smx + 128 * 136;          // prepped tile [128 n][136], linear copy
    float* sAL = (float*)(smx + 2 * 128 * 136);
    float* sAR = sAL + 128;

    const int ct  = blockIdx.y;
    const int n0  = blockIdx.x * 128;
    const int tid = threadIdx.x;
    const int lane = tid & 31;
    const int wid  = tid >> 5;

    if (tid < 128) { sAL[tid] = al[ct * 128 + tid]; sAR[tid] = ar[ct * 128 + tid]; }

#pragma unroll
    for (int i = 0; i < 8; i++) {
        int id = tid + i * 256;
        int r = id >> 4, c = id & 15;
        int n = n0 + r;
        if (n >= N_NODES) n = 0;
        *(uint4*)&As[r * 136 + c * 8] = *(const uint4*)&h16[(size_t)n * DIN + c * 8];
    }
    const uint4* wsrc = (const uint4*)(wt + (size_t)ct * WT_TILE);
#pragma unroll
    for (int i = 0; i < 9; i++) {
        int id = tid + i * 256;
        if (id < 2176) ((uint4*)Bs)[id] = wsrc[id];
    }
    __syncthreads();

    const int g = lane >> 2, q = lane & 3;
    const int m0 = wid * 16;
    float acc[16][4];
#pragma unroll
    for (int nt = 0; nt < 16; nt++)
        acc[nt][0] = acc[nt][1] = acc[nt][2] = acc[nt][3] = 0.f;

    unsigned aBase = s2u(&As[(m0 + (lane & 15)) * 136 + (lane >> 4) * 8]);
    unsigned bBase = s2u(&Bs[((lane & 7) + ((lane >> 4) << 3)) * 136 + ((lane >> 3) & 1) * 8]);

#pragma unroll
    for (int ks = 0; ks < 8; ks++) {
        unsigned a0, a1, a2, a3;
        asm volatile("ldmatrix.sync.aligned.m8n8.x4.shared.b16 {%0,%1,%2,%3}, [%4];"
                     : "=r"(a0), "=r"(a1), "=r"(a2), "=r"(a3)
                     : "r"(aBase + ks * 32));
#pragma unroll
        for (int ntp = 0; ntp < 8; ntp++) {
            unsigned b00, b01, b10, b11;
            asm volatile("ldmatrix.sync.aligned.m8n8.x4.shared.b16 {%0,%1,%2,%3}, [%4];"
                         : "=r"(b00), "=r"(b01), "=r"(b10), "=r"(b11)
                         : "r"(bBase + ntp * 4352 + ks * 32));
            int nt = 2 * ntp;
            asm volatile(
                "mma.sync.aligned.m16n8k16.row.col.f32.f16.f16.f32 "
                "{%0,%1,%2,%3}, {%4,%5,%6,%7}, {%8,%9}, {%0,%1,%2,%3};"
                : "+f"(acc[nt][0]), "+f"(acc[nt][1]), "+f"(acc[nt][2]), "+f"(acc[nt][3])
                : "r"(a0), "r"(a1), "r"(a2), "r"(a3), "r"(b00), "r"(b01));
            asm volatile(
                "mma.sync.aligned.m16n8k16.row.col.f32.f16.f16.f32 "
                "{%0,%1,%2,%3}, {%4,%5,%6,%7}, {%8,%9}, {%0,%1,%2,%3};"
                : "+f"(acc[nt + 1][0]), "+f"(acc[nt + 1][1]), "+f"(acc[nt + 1][2]), "+f"(acc[nt + 1][3])
                : "r"(a0), "r"(a1), "r"(a2), "r"(a3), "r"(b10), "r"(b11));
        }
    }

    const int rA = n0 + m0 + g, rB = rA + 8;

    // ---- el/er from fp32 accumulators ----
#pragma unroll
    for (int hh = 0; hh < HT; hh++) {
        float plA = 0.f, prA = 0.f, plB = 0.f, prB = 0.f;
#pragma unroll
        for (int j = 0; j < F / 8; j++) {
            int nt = hh * (F / 8) + j;
            int c = nt * 8 + q * 2;
            float al0 = sAL[c], al1 = sAL[c + 1];
            float ar0 = sAR[c], ar1 = sAR[c + 1];
            plA += acc[nt][0] * al0 + acc[nt][1] * al1;
            prA += acc[nt][0] * ar0 + acc[nt][1] * ar1;
            plB += acc[nt][2] * al0 + acc[nt][3] * al1;
            prB += acc[nt][2] * ar0 + acc[nt][3] * ar1;
        }
        plA += __shfl_xor_sync(~0u, plA, 1); plA += __shfl_xor_sync(~0u, plA, 2);
        prA += __shfl_xor_sync(~0u, prA, 1); prA += __shfl_xor_sync(~0u, prA, 2);
        plB += __shfl_xor_sync(~0u, plB, 1); plB += __shfl_xor_sync(~0u, plB, 2);
        prB += __shfl_xor_sync(~0u, prB, 1); prB += __shfl_xor_sync(~0u, prB, 2);
        if (q == 0) {
            int head = ct * HT + hh;
            if (rA < N_NODES) { el[rA * 4 + head] = plA; er[rA * 4 + head] = prA; }
            if (rB < N_NODES) { el[rB * 4 + head] = plB; er[rB * 4 + head] = prB; }
        }
    }

    // ---- feat: stage in smem (As), then coalesced uint4 stores ----
    __syncthreads();
#pragma unroll
    for (int nt = 0; nt < 16; nt++) {
        int c = nt * 8 + q * 2;
        *(__half2*)&As[(m0 + g) * 136 + c]     = __floats2half2_rn(acc[nt][0], acc[nt][1]);
        *(__half2*)&As[(m0 + 8 + g) * 136 + c] = __floats2half2_rn(acc[nt][2], acc[nt][3]);
    }
    __syncthreads();
#pragma unroll
    for (int i = 0; i < 8; i++) {
        int id = tid + i * 256;
        int r = id >> 4, c = id & 15;
        int n = n0 + r;
        if (n < N_NODES)
            *(uint4*)&feat[(size_t)n * HF + ct * 128 + c * 8] = *(uint4*)&As[r * 136 + c * 8];
    }
}

// ---------------- CSR build (parallel 3-kernel scan) --------------------------
__global__ void hist_kernel(const int* __restrict__ dst) {
    int e = blockIdx.x * blockDim.x + threadIdx.x;
    if (e < N_EDGES) atomicAdd(&g_cnt[dst[e]], 1);
}
__global__ void scan1_kernel() {
    __shared__ int ws[16];
    int t = threadIdx.x;
    int lane = t & 31, w = t >> 5;
    int i = blockIdx.x * 512 + t;
    int v = (i < N_NODES) ? g_cnt[i] : 0;
    if (i < N_NODES) g_cnt[i] = 0;                  // reset for next call
    int x = v;
#pragma unroll
    for (int o = 1; o < 32; o <<= 1) {
        int y = __shfl_up_sync(~0u, x, o);
        if (lane >= o) x += y;
    }
    if (lane == 31) ws[w] = x;
    __syncthreads();
    if (t < 16) {
        int s = ws[t];
#pragma unroll
        for (int o = 1; o < 16; o <<= 1) {
            int y = __shfl_up_sync(0xffffu, s, o, 16);
            if (t >= o) s += y;
        }
        ws[t] = s;
    }
    __syncthreads();
    int off = (w > 0) ? ws[w - 1] : 0;
    int incl = x + off;
    if (i < N_NODES) g_rptr[i] = incl - v;
    if (t == 511) g_bsum[blockIdx.x] = incl;
}
__global__ void scan2_kernel(int nb) {
    int t = threadIdx.x;
    int v = (t < nb) ? g_bsum[t] : 0;
    int lane = t & 31, w = t >> 5;
    __shared__ int ws[4];
    int x = v;
#pragma unroll
    for (int o = 1; o < 32; o <<= 1) {
        int y = __shfl_up_sync(~0u, x, o);
        if (lane >= o) x += y;
    }
    if (lane == 31) ws[w] = x;
    __syncthreads();
    if (t < 4) {
        int s = ws[t];
#pragma unroll
        for (int o = 1; o < 4; o <<= 1) {
            int y = __shfl_up_sync(0xfu, s, o, 4);
            if (t >= o) s += y;
        }
        ws[t] = s;
    }
    __syncthreads();
    int off = (w > 0) ? ws[w - 1] : 0;
    if (t < nb) g_bsum[t] = x + off - v;
}
__global__ void scan3_kernel() {
    int i = blockIdx.x * blockDim.x + threadIdx.x;
    if (i < N_NODES) {
        int r = g_rptr[i] + g_bsum[i >> 9];
        g_rptr[i] = r;
        g_cursor[i] = r;
    }
    if (i == 0) g_rptr[N_NODES] = N_EDGES;
}
__global__ void scatter_kernel(const int* __restrict__ src, const int* __restrict__ dst) {
    int e = blockIdx.x * blockDim.x + threadIdx.x;
    if (e >= N_EDGES) return;
    int pos = atomicAdd(&g_cursor[dst[e]], 1);
    g_srcs[pos] = src[e];
}

// ---------------- GAT aggregation: one warp per dst node ---------------------
// (exact 280.6us structure: uint2 gathers -> two independent loads per edge in
// the LAST path keep MLP high; agg is L2-bandwidth/latency bound)
template<bool LAST>
__global__ void gat_agg(const __half* __restrict__ feat, const float* __restrict__ el,
                        const float* __restrict__ er, const float* __restrict__ bias,
                        void* __restrict__ outv) {
    int warp = (blockIdx.x * blockDim.x + threadIdx.x) >> 5;
    int lane = threadIdx.x & 31;
    if (warp >= N_NODES) return;
    const int nid = warp;
    const int hl = lane & 3;
    const float er_l = __ldg(&er[nid * 4 + hl]);
    int i = __ldg(&g_rptr[nid]);
    const int end = __ldg(&g_rptr[nid + 1]);
    const uint2* f2 = (const uint2*)feat;

    float den_l = 0.f;
    float4 accA = make_float4(0, 0, 0, 0);
    float4 accB = make_float4(0, 0, 0, 0);

    if (!LAST) {
        const int hsel = lane >> 3;
#pragma unroll 4
        for (; i < end; i++) {
            int s = __ldg(&g_srcs[i]);
            float t = __ldg(&el[s * 4 + hl]) + er_l;
            float ex_l = __expf(fmaxf(t, 0.2f * t));
            den_l += ex_l;
            float ex = __shfl_sync(~0u, ex_l, hsel, 4);
            uint2 u = __ldg(&f2[(size_t)s * 32 + lane]);
            float2 fa = __half22float2(*(__half2*)&u.x);
            float2 fb = __half22float2(*(__half2*)&u.y);
            accA.x += ex * fa.x; accA.y += ex * fa.y;
            accA.z += ex * fb.x; accA.w += ex * fb.y;
        }
        float inv_l = 1.f / fmaxf(den_l, 1e-9f);
        float invh = __shfl_sync(~0u, inv_l, hsel, 4);
        int c0 = 4 * lane;
        float4 bv = *(const float4*)&bias[c0];
        float4 v;
        v.x = accA.x * invh + bv.x;
        v.y = accA.y * invh + bv.y;
        v.z = accA.z * invh + bv.z;
        v.w = accA.w * invh + bv.w;
        v.x = v.x > 0.f ? v.x : expm1f(v.x);
        v.y = v.y > 0.f ? v.y : expm1f(v.y);
        v.z = v.z > 0.f ? v.z : expm1f(v.z);
        v.w = v.w > 0.f ? v.w : expm1f(v.w);
        __half2 h01 = __floats2half2_rn(v.x, v.y);
        __half2 h23 = __floats2half2_rn(v.z, v.w);
        uint2 pack = make_uint2(*(unsigned*)&h01, *(unsigned*)&h23);
        ((uint2*)outv)[(size_t)nid * 32 + lane] = pack;
    } else {
        const int h0 = lane >> 4;
#pragma unroll 2
        for (; i < end; i++) {
            int s = __ldg(&g_srcs[i]);
            float t = __ldg(&el[s * 4 + hl]) + er_l;
            float ex_l = __expf(fmaxf(t, 0.2f * t));
            den_l += ex_l;
            float exA = __shfl_sync(~0u, ex_l, h0, 4);
            float exB = __shfl_sync(~0u, ex_l, h0 + 2, 4);
            const uint2* fr = &f2[(size_t)s * 64];
            uint2 uA = __ldg(&fr[lane]);
            uint2 uB = __ldg(&fr[32 + lane]);
            float2 a0 = __half22float2(*(__half2*)&uA.x);
            float2 a1 = __half22float2(*(__half2*)&uA.y);
            float2 b0 = __half22float2(*(__half2*)&uB.x);
            float2 b1 = __half22float2(*(__half2*)&uB.y);
            accA.x += exA * a0.x; accA.y += exA * a0.y;
            accA.z += exA * a1.x; accA.w += exA * a1.y;
            accB.x += exB * b0.x; accB.y += exB * b0.y;
            accB.z += exB * b1.x; accB.w += exB * b1.y;
        }
        float* out = (float*)outv;
        float inv_l = 1.f / fmaxf(den_l, 1e-9f);
        float invA = __shfl_sync(~0u, inv_l, h0, 4);
        float invB = __shfl_sync(~0u, inv_l, h0 + 2, 4);
        int c0 = 4 * lane;
        float p[4];
        p[0] = accA.x * invA + bias[c0]     + accB.x * invB + bias[128 + c0];
        p[1] = accA.y * invA + bias[c0 + 1] + accB.y * invB + bias[128 + c0 + 1];
        p[2] = accA.z * invA + bias[c0 + 2] + accB.z * invB + bias[128 + c0 + 2];
        p[3] = accA.w * invA + bias[c0 + 3] + accB.w * invB + bias[128 + c0 + 3];
#pragma unroll
        for (int k = 0; k < 4; k++) p[k] += __shfl_xor_sync(~0u, p[k], 16);
        if (lane < 16) {
            float4 y = make_float4(0.25f * p[0], 0.25f * p[1], 0.25f * p[2], 0.25f * p[3]);
            *(float4*)&out[(size_t)nid * 64 + c0] = y;
        }
    }
}

// ---------------- host -------------------------------------------------------
extern "C" void kernel_launch(void* const* d_in, const int* in_sizes, int n_in,
                              void* d_out, int out_size) {
    const float* x   = (const float*)d_in[0];
    const int*   src = (const int*)d_in[1];
    const int*   dst = (const int*)d_in[2];
    const float *W[4], *al[4], *ar[4], *bb[4];
    for (int i = 0; i < 4; i++) {
        W[i]  = (const float*)d_in[3 + i * 4];
        al[i] = (const float*)d_in[4 + i * 4];
        ar[i] = (const float*)d_in[5 + i * 4];
        bb[i] = (const float*)d_in[6 + i * 4];
    }

    __half *feat, *x16, *A, *B, *wt;
    float *el, *er;
    cudaGetSymbolAddress((void**)&feat, g_feath);
    cudaGetSymbolAddress((void**)&x16,  g_x16);
    cudaGetSymbolAddress((void**)&A,    g_bufA);
    cudaGetSymbolAddress((void**)&B,    g_bufB);
    cudaGetSymbolAddress((void**)&wt,   g_wt);
    cudaGetSymbolAddress((void**)&el,   g_el);
    cudaGetSymbolAddress((void**)&er,   g_er);

    const int SMEM = 2 * 128 * 136 * 2 + 2 * 128 * 4;   // 70656 B
    cudaFuncSetAttribute(tc_gemm<32>, cudaFuncAttributeMaxDynamicSharedMemorySize, SMEM);
    cudaFuncSetAttribute(tc_gemm<64>, cudaFuncAttributeMaxDynamicSharedMemorySize, SMEM);

    const int nb = (N_NODES + 511) / 512;               // 98
    const int agg_blocks = (N_NODES * 32 + 255) / 256;
    const dim3 g1((N_NODES + 127) / 128, 1), g2((N_NODES + 127) / 128, 2);

    // ---- prep + CSR; tc_gemm L1 as 4th launch (ncu captures #4) ----
    convert_x<<<N_NODES * DIN / (256 * 8), 256>>>(x, x16);
    wprep<<<dim3(32, 5), 256>>>(W[0], W[1], W[2], W[3]);
    hist_kernel<<<(N_EDGES + 511) / 512, 512>>>(dst);
    tc_gemm<32><<<g1, 256, SMEM>>>(x16, wt + 0 * WT_TILE, al[0], ar[0], feat, el, er);
    scan1_kernel<<<nb, 512>>>();
    scan2_kernel<<<1, 128>>>(nb);
    scan3_kernel<<<(N_NODES + 511) / 512, 512>>>();
    scatter_kernel<<<(N_EDGES + 511) / 512, 512>>>(src, dst);

    // layer 1 agg
    gat_agg<false><<<agg_blocks, 256>>>(feat, el, er, bb[0], A);
    // layer 2
    tc_gemm<32><<<g1, 256, SMEM>>>(A, wt + 1 * WT_TILE, al[1], ar[1], feat, el, er);
    gat_agg<false><<<agg_blocks, 256>>>(feat, el, er, bb[1], B);
    // layer 3
    tc_gemm<32><<<g1, 256, SMEM>>>(B, wt + 2 * WT_TILE, al[2], ar[2], feat, el, er);
    gat_agg<false><<<agg_blocks, 256>>>(feat, el, er, bb[2], A);
    // layer 4 (fused head-mean)
    tc_gemm<64><<<g2, 256, SMEM>>>(A, wt + 3 * WT_TILE, al[3], ar[3], feat, el, er);
    gat_agg<true><<<agg_blocks, 256>>>(feat, el, er, bb[3], d_out);
}

// round 13
// speedup vs baseline: 1.0530x; 1.0294x over previous
#include <cuda_runtime.h>
#include <cuda_fp16.h>
#include <math.h>

#define N_NODES 50000
#define N_EDGES 800000
#define DIN 128
#define NH 4
#define WT_TILE (128 * 136)   // one prepped W column-tile (halfs)

// ---------------- scratch buffers -------------------------------------------
__device__ __half g_feath[(size_t)N_NODES * 256];  // GEMM output fp16 (max HF=256)
__device__ __half g_bufA[(size_t)N_NODES * 128];   // activations fp16
__device__ __half g_bufB[(size_t)N_NODES * 128];
__device__ __half g_wt[5 * WT_TILE];               // prepped W tiles
__device__ float  g_el[(size_t)N_NODES * NH];
__device__ float  g_er[(size_t)N_NODES * NH];
__device__ int    g_cnt[N_NODES];                  // zero-init; re-zeroed by scan1
__device__ int    g_rptr[N_NODES + 1];
__device__ int    g_cursor[N_NODES];
__device__ int    g_bsum[128];
__device__ int    g_srcs[N_EDGES];

__device__ __forceinline__ unsigned s2u(const void* p) {
    unsigned a;
    asm("{ .reg .u64 t; cvta.to.shared.u64 t, %1; cvt.u32.u64 %0, t; }"
        : "=r"(a) : "l"(p));
    return a;
}

// ---------------- W prep: fp32 [K][HF] -> fp16 n-major tiles (no swizzle) ----
__global__ void wprep(const float* __restrict__ w0, const float* __restrict__ w1,
                      const float* __restrict__ w2, const float* __restrict__ w3) {
    int t = blockIdx.x * 256 + threadIdx.x;
    int y = blockIdx.y;
    const float* W; int HF, ct;
    if (y == 0)      { W = w0; HF = 128; ct = 0; }
    else if (y == 1) { W = w1; HF = 128; ct = 0; }
    else if (y == 2) { W = w2; HF = 128; ct = 0; }
    else if (y == 3) { W = w3; HF = 256; ct = 0; }
    else             { W = w3; HF = 256; ct = 1; }
    int n = t & 127, kp = t >> 7;
    int k = 2 * kp;
    float f0 = W[(size_t)k * HF + ct * 128 + n];
    float f1 = W[(size_t)(k + 1) * HF + ct * 128 + n];
    *(__half2*)&g_wt[(size_t)y * WT_TILE + n * 136 + kp * 2] = __floats2half2_rn(f0, f1);
}

// ---------------- tensor-core GEMM + fused el/er (ldmatrix mainloop) ---------
// F=32: HF=128, one column tile. F=64: HF=256, in-kernel loop over 2 column
// tiles reusing the A tile (loaded once). FP32IN: layer-1 reads fp32 x directly
// and converts in-register (no separate convert pass). Feat is staged through
// Bs (dead after each mainloop) so As survives across tiles.
template<int F, bool FP32IN>
__global__ void __launch_bounds__(256, 2)
tc_gemm(const void* __restrict__ hin, const __half* __restrict__ wt,
        const float* __restrict__ al, const float* __restrict__ ar,
        __half* __restrict__ feat, float* __restrict__ el,
        float* __restrict__ er) {
    constexpr int HF = 4 * F;
    constexpr int CT = HF / 128;           // column tiles (1 or 2)
    constexpr int HT = 128 / F;            // heads per tile
    extern __shared__ __half smx[];
    __half* As = smx;                      // [128][136] A tile (persists over ct)
    __half* Bs = smx + 128 * 136;          // W tile; reused as feat staging
    float* sAL = (float*)(smx + 2 * 128 * 136);
    float* sAR = sAL + 128;

    const int n0  = blockIdx.x * 128;
    const int tid = threadIdx.x;
    const int lane = tid & 31;
    const int wid  = tid >> 5;

    // ---- A tile load (once) ----
    if (FP32IN) {
        const float* xsrc = (const float*)hin;
#pragma unroll
        for (int i = 0; i < 8; i++) {
            int id = tid + i * 256;
            int r = id >> 4, c = id & 15;
            int n = n0 + r;
            if (n >= N_NODES) n = 0;
            const float4* xp = (const float4*)&xsrc[(size_t)n * DIN + c * 8];
            float4 a = xp[0], b = xp[1];
            __half2 h[4];
            h[0] = __floats2half2_rn(a.x, a.y);
            h[1] = __floats2half2_rn(a.z, a.w);
            h[2] = __floats2half2_rn(b.x, b.y);
            h[3] = __floats2half2_rn(b.z, b.w);
            *(uint4*)&As[r * 136 + c * 8] = *(uint4*)h;
        }
    } else {
        const __half* h16 = (const __half*)hin;
#pragma unroll
        for (int i = 0; i < 8; i++) {
            int id = tid + i * 256;
            int r = id >> 4, c = id & 15;
            int n = n0 + r;
            if (n >= N_NODES) n = 0;
            *(uint4*)&As[r * 136 + c * 8] = *(const uint4*)&h16[(size_t)n * DIN + c * 8];
        }
    }

    const int g = lane >> 2, q = lane & 3;
    const int m0 = wid * 16;
    const int rA = n0 + m0 + g, rB = rA + 8;
    unsigned aBase = s2u(&As[(m0 + (lane & 15)) * 136 + (lane >> 4) * 8]);
    unsigned bBase = s2u(&Bs[((lane & 7) + ((lane >> 4) << 3)) * 136 + ((lane >> 3) & 1) * 8]);

#pragma unroll
    for (int ct = 0; ct < CT; ct++) {
        __syncthreads();                   // prior-iter readers of sAL/Bs done
        if (tid < 128) { sAL[tid] = al[ct * 128 + tid]; sAR[tid] = ar[ct * 128 + tid]; }
        const uint4* wsrc = (const uint4*)(wt + (size_t)ct * WT_TILE);
#pragma unroll
        for (int i = 0; i < 9; i++) {
            int id = tid + i * 256;
            if (id < 2176) ((uint4*)Bs)[id] = wsrc[id];
        }
        __syncthreads();

        float acc[16][4];
#pragma unroll
        for (int nt = 0; nt < 16; nt++)
            acc[nt][0] = acc[nt][1] = acc[nt][2] = acc[nt][3] = 0.f;

#pragma unroll
        for (int ks = 0; ks < 8; ks++) {
            unsigned a0, a1, a2, a3;
            asm volatile("ldmatrix.sync.aligned.m8n8.x4.shared.b16 {%0,%1,%2,%3}, [%4];"
                         : "=r"(a0), "=r"(a1), "=r"(a2), "=r"(a3)
                         : "r"(aBase + ks * 32));
#pragma unroll
            for (int ntp = 0; ntp < 8; ntp++) {
                unsigned b00, b01, b10, b11;
                asm volatile("ldmatrix.sync.aligned.m8n8.x4.shared.b16 {%0,%1,%2,%3}, [%4];"
                             : "=r"(b00), "=r"(b01), "=r"(b10), "=r"(b11)
                             : "r"(bBase + ntp * 4352 + ks * 32));
                int nt = 2 * ntp;
                asm volatile(
                    "mma.sync.aligned.m16n8k16.row.col.f32.f16.f16.f32 "
                    "{%0,%1,%2,%3}, {%4,%5,%6,%7}, {%8,%9}, {%0,%1,%2,%3};"
                    : "+f"(acc[nt][0]), "+f"(acc[nt][1]), "+f"(acc[nt][2]), "+f"(acc[nt][3])
                    : "r"(a0), "r"(a1), "r"(a2), "r"(a3), "r"(b00), "r"(b01));
                asm volatile(
                    "mma.sync.aligned.m16n8k16.row.col.f32.f16.f16.f32 "
                    "{%0,%1,%2,%3}, {%4,%5,%6,%7}, {%8,%9}, {%0,%1,%2,%3};"
                    : "+f"(acc[nt + 1][0]), "+f"(acc[nt + 1][1]), "+f"(acc[nt + 1][2]), "+f"(acc[nt + 1][3])
                    : "r"(a0), "r"(a1), "r"(a2), "r"(a3), "r"(b10), "r"(b11));
            }
        }

        // ---- el/er from fp32 accumulators (reads sAL/sAR) ----
#pragma unroll
        for (int hh = 0; hh < HT; hh++) {
            float plA = 0.f, prA = 0.f, plB = 0.f, prB = 0.f;
#pragma unroll
            for (int j = 0; j < F / 8; j++) {
                int nt = hh * (F / 8) + j;
                int c = nt * 8 + q * 2;
                float al0 = sAL[c], al1 = sAL[c + 1];
                float ar0 = sAR[c], ar1 = sAR[c + 1];
                plA += acc[nt][0] * al0 + acc[nt][1] * al1;
                prA += acc[nt][0] * ar0 + acc[nt][1] * ar1;
                plB += acc[nt][2] * al0 + acc[nt][3] * al1;
                prB += acc[nt][2] * ar0 + acc[nt][3] * ar1;
            }
            plA += __shfl_xor_sync(~0u, plA, 1); plA += __shfl_xor_sync(~0u, plA, 2);
            prA += __shfl_xor_sync(~0u, prA, 1); prA += __shfl_xor_sync(~0u, prA, 2);
            plB += __shfl_xor_sync(~0u, plB, 1); plB += __shfl_xor_sync(~0u, plB, 2);
            prB += __shfl_xor_sync(~0u, prB, 1); prB += __shfl_xor_sync(~0u, prB, 2);
            if (q == 0) {
                int head = ct * HT + hh;
                if (rA < N_NODES) { el[rA * 4 + head] = plA; er[rA * 4 + head] = prA; }
                if (rB < N_NODES) { el[rB * 4 + head] = plB; er[rB * 4 + head] = prB; }
            }
        }

        // ---- feat: stage in Bs, then coalesced uint4 stores ----
        __syncthreads();                   // all mainloop reads of Bs done
#pragma unroll
        for (int nt = 0; nt < 16; nt++) {
            int c = nt * 8 + q * 2;
            *(__half2*)&Bs[(m0 + g) * 136 + c]     = __floats2half2_rn(acc[nt][0], acc[nt][1]);
            *(__half2*)&Bs[(m0 + 8 + g) * 136 + c] = __floats2half2_rn(acc[nt][2], acc[nt][3]);
        }
        __syncthreads();
#pragma unroll
        for (int i = 0; i < 8; i++) {
            int id = tid + i * 256;
            int r = id >> 4, c = id & 15;
            int n = n0 + r;
            if (n < N_NODES)
                *(uint4*)&feat[(size_t)n * HF + ct * 128 + c * 8] = *(uint4*)&Bs[r * 136 + c * 8];
        }
    }
}

// ---------------- CSR build (parallel 3-kernel scan) --------------------------
__global__ void hist_kernel(const int* __restrict__ dst) {
    int e = blockIdx.x * blockDim.x + threadIdx.x;
    if (e < N_EDGES) atomicAdd(&g_cnt[dst[e]], 1);
}
__global__ void scan1_kernel() {
    __shared__ int ws[16];
    int t = threadIdx.x;
    int lane = t & 31, w = t >> 5;
    int i = blockIdx.x * 512 + t;
    int v = (i < N_NODES) ? g_cnt[i] : 0;
    if (i < N_NODES) g_cnt[i] = 0;                  // reset for next call
    int x = v;
#pragma unroll
    for (int o = 1; o < 32; o <<= 1) {
        int y = __shfl_up_sync(~0u, x, o);
        if (lane >= o) x += y;
    }
    if (lane == 31) ws[w] = x;
    __syncthreads();
    if (t < 16) {
        int s = ws[t];
#pragma unroll
        for (int o = 1; o < 16; o <<= 1) {
            int y = __shfl_up_sync(0xffffu, s, o, 16);
            if (t >= o) s += y;
        }
        ws[t] = s;
    }
    __syncthreads();
    int off = (w > 0) ? ws[w - 1] : 0;
    int incl = x + off;
    if (i < N_NODES) g_rptr[i] = incl - v;
    if (t == 511) g_bsum[blockIdx.x] = incl;
}
__global__ void scan2_kernel(int nb) {
    int t = threadIdx.x;
    int v = (t < nb) ? g_bsum[t] : 0;
    int lane = t & 31, w = t >> 5;
    __shared__ int ws[4];
    int x = v;
#pragma unroll
    for (int o = 1; o < 32; o <<= 1) {
        int y = __shfl_up_sync(~0u, x, o);
        if (lane >= o) x += y;
    }
    if (lane == 31) ws[w] = x;
    __syncthreads();
    if (t < 4) {
        int s = ws[t];
#pragma unroll
        for (int o = 1; o < 4; o <<= 1) {
            int y = __shfl_up_sync(0xfu, s, o, 4);
            if (t >= o) s += y;
        }
        ws[t] = s;
    }
    __syncthreads();
    int off = (w > 0) ? ws[w - 1] : 0;
    if (t < nb) g_bsum[t] = x + off - v;
}
__global__ void scan3_kernel() {
    int i = blockIdx.x * blockDim.x + threadIdx.x;
    if (i < N_NODES) {
        int r = g_rptr[i] + g_bsum[i >> 9];
        g_rptr[i] = r;
        g_cursor[i] = r;
    }
    if (i == 0) g_rptr[N_NODES] = N_EDGES;
}
__global__ void scatter_kernel(const int* __restrict__ src, const int* __restrict__ dst) {
    int e = blockIdx.x * blockDim.x + threadIdx.x;
    if (e >= N_EDGES) return;
    int pos = atomicAdd(&g_cursor[dst[e]], 1);
    g_srcs[pos] = src[e];
}

// ---------------- GAT aggregation: one warp per dst node ---------------------
// (exact 280.6us structure — agg is at the L2 gather roofline)
template<bool LAST>
__global__ void gat_agg(const __half* __restrict__ feat, const float* __restrict__ el,
                        const float* __restrict__ er, const float* __restrict__ bias,
                        void* __restrict__ outv) {
    int warp = (blockIdx.x * blockDim.x + threadIdx.x) >> 5;
    int lane = threadIdx.x & 31;
    if (warp >= N_NODES) return;
    const int nid = warp;
    const int hl = lane & 3;
    const float er_l = __ldg(&er[nid * 4 + hl]);
    int i = __ldg(&g_rptr[nid]);
    const int end = __ldg(&g_rptr[nid + 1]);
    const uint2* f2 = (const uint2*)feat;

    float den_l = 0.f;
    float4 accA = make_float4(0, 0, 0, 0);
    float4 accB = make_float4(0, 0, 0, 0);

    if (!LAST) {
        const int hsel = lane >> 3;
#pragma unroll 4
        for (; i < end; i++) {
            int s = __ldg(&g_srcs[i]);
            float t = __ldg(&el[s * 4 + hl]) + er_l;
            float ex_l = __expf(fmaxf(t, 0.2f * t));
            den_l += ex_l;
            float ex = __shfl_sync(~0u, ex_l, hsel, 4);
            uint2 u = __ldg(&f2[(size_t)s * 32 + lane]);
            float2 fa = __half22float2(*(__half2*)&u.x);
            float2 fb = __half22float2(*(__half2*)&u.y);
            accA.x += ex * fa.x; accA.y += ex * fa.y;
            accA.z += ex * fb.x; accA.w += ex * fb.y;
        }
        float inv_l = 1.f / fmaxf(den_l, 1e-9f);
        float invh = __shfl_sync(~0u, inv_l, hsel, 4);
        int c0 = 4 * lane;
        float4 bv = *(const float4*)&bias[c0];
        float4 v;
        v.x = accA.x * invh + bv.x;
        v.y = accA.y * invh + bv.y;
        v.z = accA.z * invh + bv.z;
        v.w = accA.w * invh + bv.w;
        v.x = v.x > 0.f ? v.x : expm1f(v.x);
        v.y = v.y > 0.f ? v.y : expm1f(v.y);
        v.z = v.z > 0.f ? v.z : expm1f(v.z);
        v.w = v.w > 0.f ? v.w : expm1f(v.w);
        __half2 h01 = __floats2half2_rn(v.x, v.y);
        __half2 h23 = __floats2half2_rn(v.z, v.w);
        uint2 pack = make_uint2(*(unsigned*)&h01, *(unsigned*)&h23);
        ((uint2*)outv)[(size_t)nid * 32 + lane] = pack;
    } else {
        const int h0 = lane >> 4;
#pragma unroll 2
        for (; i < end; i++) {
            int s = __ldg(&g_srcs[i]);
            float t = __ldg(&el[s * 4 + hl]) + er_l;
            float ex_l = __expf(fmaxf(t, 0.2f * t));
            den_l += ex_l;
            float exA = __shfl_sync(~0u, ex_l, h0, 4);
            float exB = __shfl_sync(~0u, ex_l, h0 + 2, 4);
            const uint2* fr = &f2[(size_t)s * 64];
            uint2 uA = __ldg(&fr[lane]);
            uint2 uB = __ldg(&fr[32 + lane]);
            float2 a0 = __half22float2(*(__half2*)&uA.x);
            float2 a1 = __half22float2(*(__half2*)&uA.y);
            float2 b0 = __half22float2(*(__half2*)&uB.x);
            float2 b1 = __half22float2(*(__half2*)&uB.y);
            accA.x += exA * a0.x; accA.y += exA * a0.y;
            accA.z += exA * a1.x; accA.w += exA * a1.y;
            accB.x += exB * b0.x; accB.y += exB * b0.y;
            accB.z += exB * b1.x; accB.w += exB * b1.y;
        }
        float* out = (float*)outv;
        float inv_l = 1.f / fmaxf(den_l, 1e-9f);
        float invA = __shfl_sync(~0u, inv_l, h0, 4);
        float invB = __shfl_sync(~0u, inv_l, h0 + 2, 4);
        int c0 = 4 * lane;
        float p[4];
        p[0] = accA.x * invA + bias[c0]     + accB.x * invB + bias[128 + c0];
        p[1] = accA.y * invA + bias[c0 + 1] + accB.y * invB + bias[128 + c0 + 1];
        p[2] = accA.z * invA + bias[c0 + 2] + accB.z * invB + bias[128 + c0 + 2];
        p[3] = accA.w * invA + bias[c0 + 3] + accB.w * invB + bias[128 + c0 + 3];
#pragma unroll
        for (int k = 0; k < 4; k++) p[k] += __shfl_xor_sync(~0u, p[k], 16);
        if (lane < 16) {
            float4 y = make_float4(0.25f * p[0], 0.25f * p[1], 0.25f * p[2], 0.25f * p[3]);
            *(float4*)&out[(size_t)nid * 64 + c0] = y;
        }
    }
}

// ---------------- host -------------------------------------------------------
extern "C" void kernel_launch(void* const* d_in, const int* in_sizes, int n_in,
                              void* d_out, int out_size) {
    const float* x   = (const float*)d_in[0];
    const int*   src = (const int*)d_in[1];
    const int*   dst = (const int*)d_in[2];
    const float *W[4], *al[4], *ar[4], *bb[4];
    for (int i = 0; i < 4; i++) {
        W[i]  = (const float*)d_in[3 + i * 4];
        al[i] = (const float*)d_in[4 + i * 4];
        ar[i] = (const float*)d_in[5 + i * 4];
        bb[i] = (const float*)d_in[6 + i * 4];
    }

    __half *feat, *A, *B, *wt;
    float *el, *er;
    cudaGetSymbolAddress((void**)&feat, g_feath);
    cudaGetSymbolAddress((void**)&A,    g_bufA);
    cudaGetSymbolAddress((void**)&B,    g_bufB);
    cudaGetSymbolAddress((void**)&wt,   g_wt);
    cudaGetSymbolAddress((void**)&el,   g_el);
    cudaGetSymbolAddress((void**)&er,   g_er);

    const int SMEM = 2 * 128 * 136 * 2 + 2 * 128 * 4;   // 70656 B
    cudaFuncSetAttribute((tc_gemm<32, true>),  cudaFuncAttributeMaxDynamicSharedMemorySize, SMEM);
    cudaFuncSetAttribute((tc_gemm<32, false>), cudaFuncAttributeMaxDynamicSharedMemorySize, SMEM);
    cudaFuncSetAttribute((tc_gemm<64, false>), cudaFuncAttributeMaxDynamicSharedMemorySize, SMEM);

    const int nb = (N_NODES + 511) / 512;               // 98
    const int agg_blocks = (N_NODES * 32 + 255) / 256;
    const dim3 g1((N_NODES + 127) / 128, 1);

    // ---- prep + CSR; tc_gemm L1 (fp32-in) as 4th launch (ncu captures #4) ----
    wprep<<<dim3(32, 5), 256>>>(W[0], W[1], W[2], W[3]);
    hist_kernel<<<(N_EDGES + 511) / 512, 512>>>(dst);
    scan1_kernel<<<nb, 512>>>();
    tc_gemm<32, true><<<g1, 256, SMEM>>>(x, wt + 0 * WT_TILE, al[0], ar[0], feat, el, er);
    scan2_kernel<<<1, 128>>>(nb);
    scan3_kernel<<<(N_NODES + 511) / 512, 512>>>();
    scatter_kernel<<<(N_EDGES + 511) / 512, 512>>>(src, dst);

    // layer 1 agg
    gat_agg<false><<<agg_blocks, 256>>>(feat, el, er, bb[0], A);
    // layer 2
    tc_gemm<32, false><<<g1, 256, SMEM>>>(A, wt + 1 * WT_TILE, al[1], ar[1], feat, el, er);
    gat_agg<false><<<agg_blocks, 256>>>(feat, el, er, bb[1], B);
    // layer 3
    tc_gemm<32, false><<<g1, 256, SMEM>>>(B, wt + 2 * WT_TILE, al[2], ar[2], feat, el, er);
    gat_agg<false><<<agg_blocks, 256>>>(feat, el, er, bb[2], A);
    // layer 4: both column tiles in one grid (A tile loaded once)
    tc_gemm<64, false><<<g1, 256, SMEM>>>(A, wt + 3 * WT_TILE, al[3], ar[3], feat, el, er);
    gat_agg<true><<<agg_blocks, 256>>>(feat, el, er, bb[3], d_out);
}

// round 14
// speedup vs baseline: 1.0788x; 1.0245x over previous
#include <cuda_runtime.h>
#include <cuda_fp16.h>
#include <math.h>

#define N_NODES 50000
#define N_EDGES 800000
#define DIN 128
#define NH 4
#define WT_TILE (128 * 136)   // one prepped W column-tile (halfs)

// ---------------- scratch buffers -------------------------------------------
__device__ __half g_feath[(size_t)N_NODES * 256];  // GEMM output fp16 (max HF=256)
__device__ __half g_bufA[(size_t)N_NODES * 128];   // activations fp16
__device__ __half g_bufB[(size_t)N_NODES * 128];
__device__ __half g_wt[5 * WT_TILE];               // prepped W tiles
__device__ float  g_el[(size_t)N_NODES * NH];
__device__ float  g_er[(size_t)N_NODES * NH];
__device__ int    g_cnt[N_NODES];                  // zero-init; re-zeroed by scan1
__device__ int    g_rptr[N_NODES + 1];
__device__ int    g_cursor[N_NODES];
__device__ int    g_bsum[128];
__device__ int    g_srcs[N_EDGES];

// ---------------- streams/events for graph fork-join (host-side objects) -----
struct ForkCtx {
    cudaStream_t s1;
    cudaEvent_t evRoot, evJoin;
    ForkCtx() {
        cudaStreamCreateWithFlags(&s1, cudaStreamNonBlocking);
        cudaEventCreateWithFlags(&evRoot, cudaEventDisableTiming);
        cudaEventCreateWithFlags(&evJoin, cudaEventDisableTiming);
    }
};
static ForkCtx g_fork;

__device__ __forceinline__ unsigned s2u(const void* p) {
    unsigned a;
    asm("{ .reg .u64 t; cvta.to.shared.u64 t, %1; cvt.u32.u64 %0, t; }"
        : "=r"(a) : "l"(p));
    return a;
}

// ---------------- W prep: fp32 [K][HF] -> fp16 n-major tiles (no swizzle) ----
__global__ void wprep(const float* __restrict__ w0, const float* __restrict__ w1,
                      const float* __restrict__ w2, const float* __restrict__ w3) {
    int t = blockIdx.x * 256 + threadIdx.x;
    int y = blockIdx.y;
    const float* W; int HF, ct;
    if (y == 0)      { W = w0; HF = 128; ct = 0; }
    else if (y == 1) { W = w1; HF = 128; ct = 0; }
    else if (y == 2) { W = w2; HF = 128; ct = 0; }
    else if (y == 3) { W = w3; HF = 256; ct = 0; }
    else             { W = w3; HF = 256; ct = 1; }
    int n = t & 127, kp = t >> 7;
    int k = 2 * kp;
    float f0 = W[(size_t)k * HF + ct * 128 + n];
    float f1 = W[(size_t)(k + 1) * HF + ct * 128 + n];
    *(__half2*)&g_wt[(size_t)y * WT_TILE + n * 136 + kp * 2] = __floats2half2_rn(f0, f1);
}

// ---------------- tensor-core GEMM + fused el/er (ldmatrix mainloop) ---------
template<int F, bool FP32IN>
__global__ void __launch_bounds__(256, 2)
tc_gemm(const void* __restrict__ hin, const __half* __restrict__ wt,
        const float* __restrict__ al, const float* __restrict__ ar,
        __half* __restrict__ feat, float* __restrict__ el,
        float* __restrict__ er) {
    constexpr int HF = 4 * F;
    constexpr int CT = HF / 128;           // column tiles (1 or 2)
    constexpr int HT = 128 / F;            // heads per tile
    extern __shared__ __half smx[];
    __half* As = smx;                      // [128][136] A tile (persists over ct)
    __half* Bs = smx + 128 * 136;          // W tile; reused as feat staging
    float* sAL = (float*)(smx + 2 * 128 * 136);
    float* sAR = sAL + 128;

    const int n0  = blockIdx.x * 128;
    const int tid = threadIdx.x;
    const int lane = tid & 31;
    const int wid  = tid >> 5;

    // ---- A tile load (once) ----
    if (FP32IN) {
        const float* xsrc = (const float*)hin;
#pragma unroll
        for (int i = 0; i < 8; i++) {
            int id = tid + i * 256;
            int r = id >> 4, c = id & 15;
            int n = n0 + r;
            if (n >= N_NODES) n = 0;
            const float4* xp = (const float4*)&xsrc[(size_t)n * DIN + c * 8];
            float4 a = xp[0], b = xp[1];
            __half2 h[4];
            h[0] = __floats2half2_rn(a.x, a.y);
            h[1] = __floats2half2_rn(a.z, a.w);
            h[2] = __floats2half2_rn(b.x, b.y);
            h[3] = __floats2half2_rn(b.z, b.w);
            *(uint4*)&As[r * 136 + c * 8] = *(uint4*)h;
        }
    } else {
        const __half* h16 = (const __half*)hin;
#pragma unroll
        for (int i = 0; i < 8; i++) {
            int id = tid + i * 256;
            int r = id >> 4, c = id & 15;
            int n = n0 + r;
            if (n >= N_NODES) n = 0;
            *(uint4*)&As[r * 136 + c * 8] = *(const uint4*)&h16[(size_t)n * DIN + c * 8];
        }
    }

    const int g = lane >> 2, q = lane & 3;
    const int m0 = wid * 16;
    const int rA = n0 + m0 + g, rB = rA + 8;
    unsigned aBase = s2u(&As[(m0 + (lane & 15)) * 136 + (lane >> 4) * 8]);
    unsigned bBase = s2u(&Bs[((lane & 7) + ((lane >> 4) << 3)) * 136 + ((lane >> 3) & 1) * 8]);

#pragma unroll
    for (int ct = 0; ct < CT; ct++) {
        __syncthreads();                   // prior-iter readers of sAL/Bs done
        if (tid < 128) { sAL[tid] = al[ct * 128 + tid]; sAR[tid] = ar[ct * 128 + tid]; }
        const uint4* wsrc = (const uint4*)(wt + (size_t)ct * WT_TILE);
#pragma unroll
        for (int i = 0; i < 9; i++) {
            int id = tid + i * 256;
            if (id < 2176) ((uint4*)Bs)[id] = wsrc[id];
        }
        __syncthreads();

        float acc[16][4];
#pragma unroll
        for (int nt = 0; nt < 16; nt++)
            acc[nt][0] = acc[nt][1] = acc[nt][2] = acc[nt][3] = 0.f;

#pragma unroll
        for (int ks = 0; ks < 8; ks++) {
            unsigned a0, a1, a2, a3;
            asm volatile("ldmatrix.sync.aligned.m8n8.x4.shared.b16 {%0,%1,%2,%3}, [%4];"
                         : "=r"(a0), "=r"(a1), "=r"(a2), "=r"(a3)
                         : "r"(aBase + ks * 32));
#pragma unroll
            for (int ntp = 0; ntp < 8; ntp++) {
                unsigned b00, b01, b10, b11;
                asm volatile("ldmatrix.sync.aligned.m8n8.x4.shared.b16 {%0,%1,%2,%3}, [%4];"
                             : "=r"(b00), "=r"(b01), "=r"(b10), "=r"(b11)
                             : "r"(bBase + ntp * 4352 + ks * 32));
                int nt = 2 * ntp;
                asm volatile(
                    "mma.sync.aligned.m16n8k16.row.col.f32.f16.f16.f32 "
                    "{%0,%1,%2,%3}, {%4,%5,%6,%7}, {%8,%9}, {%0,%1,%2,%3};"
                    : "+f"(acc[nt][0]), "+f"(acc[nt][1]), "+f"(acc[nt][2]), "+f"(acc[nt][3])
                    : "r"(a0), "r"(a1), "r"(a2), "r"(a3), "r"(b00), "r"(b01));
                asm volatile(
                    "mma.sync.aligned.m16n8k16.row.col.f32.f16.f16.f32 "
                    "{%0,%1,%2,%3}, {%4,%5,%6,%7}, {%8,%9}, {%0,%1,%2,%3};"
                    : "+f"(acc[nt + 1][0]), "+f"(acc[nt + 1][1]), "+f"(acc[nt + 1][2]), "+f"(acc[nt + 1][3])
                    : "r"(a0), "r"(a1), "r"(a2), "r"(a3), "r"(b10), "r"(b11));
            }
        }

        // ---- el/er from fp32 accumulators ----
#pragma unroll
        for (int hh = 0; hh < HT; hh++) {
            float plA = 0.f, prA = 0.f, plB = 0.f, prB = 0.f;
#pragma unroll
            for (int j = 0; j < F / 8; j++) {
                int nt = hh * (F / 8) + j;
                int c = nt * 8 + q * 2;
                float al0 = sAL[c], al1 = sAL[c + 1];
                float ar0 = sAR[c], ar1 = sAR[c + 1];
                plA += acc[nt][0] * al0 + acc[nt][1] * al1;
                prA += acc[nt][0] * ar0 + acc[nt][1] * ar1;
                plB += acc[nt][2] * al0 + acc[nt][3] * al1;
                prB += acc[nt][2] * ar0 + acc[nt][3] * ar1;
            }
            plA += __shfl_xor_sync(~0u, plA, 1); plA += __shfl_xor_sync(~0u, plA, 2);
            prA += __shfl_xor_sync(~0u, prA, 1); prA += __shfl_xor_sync(~0u, prA, 2);
            plB += __shfl_xor_sync(~0u, plB, 1); plB += __shfl_xor_sync(~0u, plB, 2);
            prB += __shfl_xor_sync(~0u, prB, 1); prB += __shfl_xor_sync(~0u, prB, 2);
            if (q == 0) {
                int head = ct * HT + hh;
                if (rA < N_NODES) { el[rA * 4 + head] = plA; er[rA * 4 + head] = prA; }
                if (rB < N_NODES) { el[rB * 4 + head] = plB; er[rB * 4 + head] = prB; }
            }
        }

        // ---- feat: stage in Bs, then coalesced uint4 stores ----
        __syncthreads();                   // all mainloop reads of Bs done
#pragma unroll
        for (int nt = 0; nt < 16; nt++) {
            int c = nt * 8 + q * 2;
            *(__half2*)&Bs[(m0 + g) * 136 + c]     = __floats2half2_rn(acc[nt][0], acc[nt][1]);
            *(__half2*)&Bs[(m0 + 8 + g) * 136 + c] = __floats2half2_rn(acc[nt][2], acc[nt][3]);
        }
        __syncthreads();
#pragma unroll
        for (int i = 0; i < 8; i++) {
            int id = tid + i * 256;
            int r = id >> 4, c = id & 15;
            int n = n0 + r;
            if (n < N_NODES)
                *(uint4*)&feat[(size_t)n * HF + ct * 128 + c * 8] = *(uint4*)&Bs[r * 136 + c * 8];
        }
    }
}

// ---------------- CSR build (parallel 3-kernel scan) --------------------------
__global__ void hist_kernel(const int* __restrict__ dst) {
    int e = blockIdx.x * blockDim.x + threadIdx.x;
    if (e < N_EDGES) atomicAdd(&g_cnt[dst[e]], 1);
}
__global__ void scan1_kernel() {
    __shared__ int ws[16];
    int t = threadIdx.x;
    int lane = t & 31, w = t >> 5;
    int i = blockIdx.x * 512 + t;
    int v = (i < N_NODES) ? g_cnt[i] : 0;
    if (i < N_NODES) g_cnt[i] = 0;                  // reset for next call
    int x = v;
#pragma unroll
    for (int o = 1; o < 32; o <<= 1) {
        int y = __shfl_up_sync(~0u, x, o);
        if (lane >= o) x += y;
    }
    if (lane == 31) ws[w] = x;
    __syncthreads();
    if (t < 16) {
        int s = ws[t];
#pragma unroll
        for (int o = 1; o < 16; o <<= 1) {
            int y = __shfl_up_sync(0xffffu, s, o, 16);
            if (t >= o) s += y;
        }
        ws[t] = s;
    }
    __syncthreads();
    int off = (w > 0) ? ws[w - 1] : 0;
    int incl = x + off;
    if (i < N_NODES) g_rptr[i] = incl - v;
    if (t == 511) g_bsum[blockIdx.x] = incl;
}
__global__ void scan2_kernel(int nb) {
    int t = threadIdx.x;
    int v = (t < nb) ? g_bsum[t] : 0;
    int lane = t & 31, w = t >> 5;
    __shared__ int ws[4];
    int x = v;
#pragma unroll
    for (int o = 1; o < 32; o <<= 1) {
        int y = __shfl_up_sync(~0u, x, o);
        if (lane >= o) x += y;
    }
    if (lane == 31) ws[w] = x;
    __syncthreads();
    if (t < 4) {
        int s = ws[t];
#pragma unroll
        for (int o = 1; o < 4; o <<= 1) {
            int y = __shfl_up_sync(0xfu, s, o, 4);
            if (t >= o) s += y;
        }
        ws[t] = s;
    }
    __syncthreads();
    int off = (w > 0) ? ws[w - 1] : 0;
    if (t < nb) g_bsum[t] = x + off - v;
}
__global__ void scan3_kernel() {
    int i = blockIdx.x * blockDim.x + threadIdx.x;
    if (i < N_NODES) {
        int r = g_rptr[i] + g_bsum[i >> 9];
        g_rptr[i] = r;
        g_cursor[i] = r;
    }
    if (i == 0) g_rptr[N_NODES] = N_EDGES;
}
__global__ void scatter_kernel(const int* __restrict__ src, const int* __restrict__ dst) {
    int e = blockIdx.x * blockDim.x + threadIdx.x;
    if (e >= N_EDGES) return;
    int pos = atomicAdd(&g_cursor[dst[e]], 1);
    g_srcs[pos] = src[e];
}

// ---------------- GAT aggregation: one warp per dst node ---------------------
template<bool LAST>
__global__ void gat_agg(const __half* __restrict__ feat, const float* __restrict__ el,
                        const float* __restrict__ er, const float* __restrict__ bias,
                        void* __restrict__ outv) {
    int warp = (blockIdx.x * blockDim.x + threadIdx.x) >> 5;
    int lane = threadIdx.x & 31;
    if (warp >= N_NODES) return;
    const int nid = warp;
    const int hl = lane & 3;
    const float er_l = __ldg(&er[nid * 4 + hl]);
    int i = __ldg(&g_rptr[nid]);
    const int end = __ldg(&g_rptr[nid + 1]);
    const uint2* f2 = (const uint2*)feat;

    float den_l = 0.f;
    float4 accA = make_float4(0, 0, 0, 0);
    float4 accB = make_float4(0, 0, 0, 0);

    if (!LAST) {
        const int hsel = lane >> 3;
#pragma unroll 4
        for (; i < end; i++) {
            int s = __ldg(&g_srcs[i]);
            float t = __ldg(&el[s * 4 + hl]) + er_l;
            float ex_l = __expf(fmaxf(t, 0.2f * t));
            den_l += ex_l;
            float ex = __shfl_sync(~0u, ex_l, hsel, 4);
            uint2 u = __ldg(&f2[(size_t)s * 32 + lane]);
            float2 fa = __half22float2(*(__half2*)&u.x);
            float2 fb = __half22float2(*(__half2*)&u.y);
            accA.x += ex * fa.x; accA.y += ex * fa.y;
            accA.z += ex * fb.x; accA.w += ex * fb.y;
        }
        float inv_l = 1.f / fmaxf(den_l, 1e-9f);
        float invh = __shfl_sync(~0u, inv_l, hsel, 4);
        int c0 = 4 * lane;
        float4 bv = *(const float4*)&bias[c0];
        float4 v;
        v.x = accA.x * invh + bv.x;
        v.y = accA.y * invh + bv.y;
        v.z = accA.z * invh + bv.z;
        v.w = accA.w * invh + bv.w;
        v.x = v.x > 0.f ? v.x : expm1f(v.x);
        v.y = v.y > 0.f ? v.y : expm1f(v.y);
        v.z = v.z > 0.f ? v.z : expm1f(v.z);
        v.w = v.w > 0.f ? v.w : expm1f(v.w);
        __half2 h01 = __floats2half2_rn(v.x, v.y);
        __half2 h23 = __floats2half2_rn(v.z, v.w);
        uint2 pack = make_uint2(*(unsigned*)&h01, *(unsigned*)&h23);
        ((uint2*)outv)[(size_t)nid * 32 + lane] = pack;
    } else {
        const int h0 = lane >> 4;
#pragma unroll 2
        for (; i < end; i++) {
            int s = __ldg(&g_srcs[i]);
            float t = __ldg(&el[s * 4 + hl]) + er_l;
            float ex_l = __expf(fmaxf(t, 0.2f * t));
            den_l += ex_l;
            float exA = __shfl_sync(~0u, ex_l, h0, 4);
            float exB = __shfl_sync(~0u, ex_l, h0 + 2, 4);
            const uint2* fr = &f2[(size_t)s * 64];
            uint2 uA = __ldg(&fr[lane]);
            uint2 uB = __ldg(&fr[32 + lane]);
            float2 a0 = __half22float2(*(__half2*)&uA.x);
            float2 a1 = __half22float2(*(__half2*)&uA.y);
            float2 b0 = __half22float2(*(__half2*)&uB.x);
            float2 b1 = __half22float2(*(__half2*)&uB.y);
            accA.x += exA * a0.x; accA.y += exA * a0.y;
            accA.z += exA * a1.x; accA.w += exA * a1.y;
            accB.x += exB * b0.x; accB.y += exB * b0.y;
            accB.z += exB * b1.x; accB.w += exB * b1.y;
        }
        float* out = (float*)outv;
        float inv_l = 1.f / fmaxf(den_l, 1e-9f);
        float invA = __shfl_sync(~0u, inv_l, h0, 4);
        float invB = __shfl_sync(~0u, inv_l, h0 + 2, 4);
        int c0 = 4 * lane;
        float p[4];
        p[0] = accA.x * invA + bias[c0]     + accB.x * invB + bias[128 + c0];
        p[1] = accA.y * invA + bias[c0 + 1] + accB.y * invB + bias[128 + c0 + 1];
        p[2] = accA.z * invA + bias[c0 + 2] + accB.z * invB + bias[128 + c0 + 2];
        p[3] = accA.w * invA + bias[c0 + 3] + accB.w * invB + bias[128 + c0 + 3];
#pragma unroll
        for (int k = 0; k < 4; k++) p[k] += __shfl_xor_sync(~0u, p[k], 16);
        if (lane < 16) {
            float4 y = make_float4(0.25f * p[0], 0.25f * p[1], 0.25f * p[2], 0.25f * p[3]);
            *(float4*)&out[(size_t)nid * 64 + c0] = y;
        }
    }
}

// ---------------- host -------------------------------------------------------
extern "C" void kernel_launch(void* const* d_in, const int* in_sizes, int n_in,
                              void* d_out, int out_size) {
    const float* x   = (const float*)d_in[0];
    const int*   src = (const int*)d_in[1];
    const int*   dst = (const int*)d_in[2];
    const float *W[4], *al[4], *ar[4], *bb[4];
    for (int i = 0; i < 4; i++) {
        W[i]  = (const float*)d_in[3 + i * 4];
        al[i] = (const float*)d_in[4 + i * 4];
        ar[i] = (const float*)d_in[5 + i * 4];
        bb[i] = (const float*)d_in[6 + i * 4];
    }

    __half *feat, *A, *B, *wt;
    float *el, *er;
    cudaGetSymbolAddress((void**)&feat, g_feath);
    cudaGetSymbolAddress((void**)&A,    g_bufA);
    cudaGetSymbolAddress((void**)&B,    g_bufB);
    cudaGetSymbolAddress((void**)&wt,   g_wt);
    cudaGetSymbolAddress((void**)&el,   g_el);
    cudaGetSymbolAddress((void**)&er,   g_er);

    const int SMEM = 2 * 128 * 136 * 2 + 2 * 128 * 4;   // 70656 B
    cudaFuncSetAttribute((tc_gemm<32, true>),  cudaFuncAttributeMaxDynamicSharedMemorySize, SMEM);
    cudaFuncSetAttribute((tc_gemm<32, false>), cudaFuncAttributeMaxDynamicSharedMemorySize, SMEM);
    cudaFuncSetAttribute((tc_gemm<64, false>), cudaFuncAttributeMaxDynamicSharedMemorySize, SMEM);

    const int nb = (N_NODES + 511) / 512;               // 98
    const int agg_blocks = (N_NODES * 32 + 255) / 256;
    const dim3 g1((N_NODES + 127) / 128, 1);

    // ---- fork: CSR chain on side stream, wprep+L1 GEMM on main stream ----
    cudaEventRecord(g_fork.evRoot, 0);
    cudaStreamWaitEvent(g_fork.s1, g_fork.evRoot, 0);

    hist_kernel<<<(N_EDGES + 511) / 512, 512, 0, g_fork.s1>>>(dst);
    scan1_kernel<<<nb, 512, 0, g_fork.s1>>>();
    scan2_kernel<<<1, 128, 0, g_fork.s1>>>(nb);
    scan3_kernel<<<(N_NODES + 511) / 512, 512, 0, g_fork.s1>>>();
    scatter_kernel<<<(N_EDGES + 511) / 512, 512, 0, g_fork.s1>>>(src, dst);
    cudaEventRecord(g_fork.evJoin, g_fork.s1);

    wprep<<<dim3(32, 5), 256>>>(W[0], W[1], W[2], W[3]);
    tc_gemm<32, true><<<g1, 256, SMEM>>>(x, wt + 0 * WT_TILE, al[0], ar[0], feat, el, er);

    cudaStreamWaitEvent(0, g_fork.evJoin, 0);           // join before agg

    // layer 1 agg
    gat_agg<false><<<agg_blocks, 256>>>(feat, el, er, bb[0], A);
    // layer 2
    tc_gemm<32, false><<<g1, 256, SMEM>>>(A, wt + 1 * WT_TILE, al[1], ar[1], feat, el, er);
    gat_agg<false><<<agg_blocks, 256>>>(feat, el, er, bb[1], B);
    // layer 3
    tc_gemm<32, false><<<g1, 256, SMEM>>>(B, wt + 2 * WT_TILE, al[2], ar[2], feat, el, er);
    gat_agg<false><<<agg_blocks, 256>>>(feat, el, er, bb[2], A);
    // layer 4: both column tiles in one grid (A tile loaded once)
    tc_gemm<64, false><<<g1, 256, SMEM>>>(A, wt + 3 * WT_TILE, al[3], ar[3], feat, el, er);
    gat_agg<true><<<agg_blocks, 256>>>(feat, el, er, bb[3], d_out);
}